// round 15
// baseline (speedup 1.0000x reference)
#include <cuda_runtime.h>
#include <math.h>

#define BB   4
#define NN   1024
#define KNN  30
#define MM   8
#define CINV 9
#define OO   64
#define FE   320
#define PC   512          // M*O
#define BN_SCALE 0.99999500003749972f

// ---------------- packed f32x2 helpers (u64 carriers) ----------------
typedef unsigned long long u64;
__device__ __forceinline__ void ffma2(u64& d, u64 a, u64 b){
    asm("fma.rn.f32x2 %0, %1, %2, %0;" : "+l"(d) : "l"(a), "l"(b));
}
__device__ __forceinline__ u64 pack2(float lo, float hi){
    u64 d; asm("mov.b64 %0, {%1,%2};" : "=l"(d) : "f"(lo), "f"(hi)); return d;
}
__device__ __forceinline__ void unpack2(float& lo, float& hi, u64 d){
    asm("mov.b64 {%0,%1}, %2;" : "=f"(lo), "=f"(hi) : "l"(d));
}

// ---------------- device scratch (no allocs allowed) ----------------
__device__ float g_xt[BB*NN*CINV];
__device__ float g_sq[BB*NN];
__device__ int   g_idx[BB*NN*KNN];
__device__ float g_xyz[BB*NN*KNN*28];
__device__ float g_feats[BB*NN*FE];
__device__ float g_score[4*BB*NN*KNN*MM];  // [l][bn][k][m]
__device__ float g_A[BB*NN*1024];          // per layer: [n][u]  (u<512: G, u>=512: S*f)
__device__ float g_W[4*1024*OO];           // [l][u][o]

// ---------------- 1) transpose + sq (+ zero out) ----------------
__global__ void k_prep(const float* __restrict__ x, float* __restrict__ out){
    int t = blockIdx.x*blockDim.x + threadIdx.x;
    if (t < BB*PC) out[t] = 0.f;
    if (t >= BB*NN) return;
    int b = t >> 10, n = t & 1023;
    float s = 0.f;
#pragma unroll
    for (int c = 0; c < CINV; c++){
        float v = x[(b*CINV + c)*NN + n];
        g_xt[t*CINV + c] = v;
        s += v*v;
    }
    g_sq[t] = s;
}

// ---------------- 2) knn top-K: block per point, argmax extraction ----------------
__global__ void k_knn(){
    __shared__ unsigned long long keys[NN];   // 8KB
    __shared__ unsigned long long wmax[8];
    __shared__ float sc[CINV];
    int bn  = blockIdx.x;
    int b   = bn >> 10;
    int tid = threadIdx.x;                    // 256
    if (tid < CINV) sc[tid] = g_xt[bn*CINV + tid];
    __syncthreads();
    float c[CINV];
#pragma unroll
    for (int t = 0; t < CINV; t++) c[t] = sc[t];
    float sqi = g_sq[bn];
    for (int j = tid; j < NN; j += 256){
        const float* p = &g_xt[(b*NN + j)*CINV];
        float d = 0.f;
#pragma unroll
        for (int t = 0; t < CINV; t++) d += c[t]*p[t];
        float v = 2.0f*d - sqi - g_sq[b*NN + j];
        int iv = __float_as_int(v);
        unsigned int u = (iv >= 0) ? ((unsigned)iv | 0x80000000u) : ~((unsigned)iv);
        keys[j] = ((unsigned long long)u << 32) | (unsigned)(NN - j);
    }
    __syncthreads();
    for (int s = 0; s < KNN; s++){
        unsigned long long m = 0ULL;
#pragma unroll
        for (int r = 0; r < NN/256; r++){
            unsigned long long kk = keys[tid + r*256];
            if (kk > m) m = kk;
        }
#pragma unroll
        for (int off = 16; off; off >>= 1){
            unsigned long long o = __shfl_down_sync(0xFFFFFFFFu, m, off);
            if (o > m) m = o;
        }
        if ((tid & 31) == 0) wmax[tid >> 5] = m;
        __syncthreads();
        if (tid == 0){
            unsigned long long mm = wmax[0];
#pragma unroll
            for (int w = 1; w < 8; w++) if (wmax[w] > mm) mm = wmax[w];
            int j = NN - (int)(mm & 0xFFFFFFFFULL);
            g_idx[bn*KNN + s] = j;
            keys[j] = 0ULL;
        }
        __syncthreads();
    }
}

// ---------------- 3) xyz build + conv1->bn->relu->max_k (4 points/block) ----------------
__global__ void k_edge(const float* __restrict__ w1, const float* __restrict__ b1){
    int p0  = blockIdx.x*4;                // 1024 blocks
    int tid = threadIdx.x;                 // 256
    int lp  = tid >> 6;                    // local point 0..3
    int o   = tid & 63;                    // channel
    __shared__ float s_w1[64*18];
    __shared__ float s_b1[64];
    __shared__ float s_gf[4][KNN][18];
    __shared__ float s_ctr[4][CINV];
    for (int q = tid; q < 64*18; q += 256) s_w1[q] = w1[q];
    if (tid < 64) s_b1[tid] = b1[tid];
    if (tid < 4*CINV) s_ctr[tid/CINV][tid%CINV] = g_xt[(p0 + tid/CINV)*CINV + tid%CINV];
    __syncthreads();
    if (tid < 4*KNN){
        int lp2 = tid / KNN;
        int k   = tid - lp2*KNN;
        int bn  = p0 + lp2;
        int b   = bn >> 10;
        int j   = g_idx[bn*KNN + k];
        float nb[CINV], df[CINV]; float ss = 0.f;
#pragma unroll
        for (int t = 0; t < CINV; t++){
            float ct = s_ctr[lp2][t];
            nb[t] = g_xt[(b*NN + j)*CINV + t];
            df[t] = nb[t] - ct;
            ss += df[t]*df[t];
        }
        float* xz = &g_xyz[(bn*KNN + k)*28];
#pragma unroll
        for (int t = 0; t < CINV; t++){
            xz[t]      = df[t];
            xz[9 + t]  = nb[t];
            xz[18 + t] = s_ctr[lp2][t];
            s_gf[lp2][k][t]     = df[t];
            s_gf[lp2][k][9 + t] = s_ctr[lp2][t];
        }
        xz[27] = sqrtf(ss);
    }
    __syncthreads();
    float w[18];
#pragma unroll
    for (int t = 0; t < 18; t++) w[t] = s_w1[o*18 + t];
    float bias = s_b1[o];
    float mx = 0.f;
    for (int k = 0; k < KNN; k++){
        float d = bias;
#pragma unroll
        for (int t = 0; t < 18; t++) d += s_gf[lp][k][t]*w[t];
        mx = fmaxf(mx, d*BN_SCALE);
    }
    g_feats[(p0 + lp)*FE + o] = mx;
}

// ---------------- 3b) scorenet: one layer per block ----------------
__global__ void k_score(const float* __restrict__ hw, const float* __restrict__ ow,
                        const float* __restrict__ ob){
    __shared__ float s_hw[448];
    __shared__ float s_ow[128];
    __shared__ float s_ob[8];
    int tid = threadIdx.x;                 // 256
    int l   = blockIdx.x & 3;
    int item = (blockIdx.x >> 2)*256 + tid;    // bn*KNN + k
    for (int q = tid; q < 448; q += 256) s_hw[q] = hw[l*448 + q];
    if (tid < 128) s_ow[tid] = ow[l*128 + tid];
    if (tid < 8)   s_ob[tid] = ob[l*8 + tid];
    __syncthreads();
    float xr[28];
    const float4* xz4 = (const float4*)(g_xyz + item*28);
#pragma unroll
    for (int v = 0; v < 7; v++) ((float4*)xr)[v] = xz4[v];
    float hid[16];
#pragma unroll
    for (int h = 0; h < 16; h++){
        const float4* hw4 = (const float4*)&s_hw[h*28];
        float d = 0.f;
#pragma unroll
        for (int t4 = 0; t4 < 7; t4++){
            float4 w4 = hw4[t4];
            d += xr[4*t4]*w4.x + xr[4*t4+1]*w4.y + xr[4*t4+2]*w4.z + xr[4*t4+3]*w4.w;
        }
        hid[h] = fmaxf(d*BN_SCALE, 0.f);
    }
    float lg[8]; float mxl = -3.4e38f;
#pragma unroll
    for (int m = 0; m < 8; m++){
        const float4* ow4 = (const float4*)&s_ow[m*16];
        float d = s_ob[m];
#pragma unroll
        for (int h4 = 0; h4 < 4; h4++){
            float4 w4 = ow4[h4];
            d += hid[4*h4]*w4.x + hid[4*h4+1]*w4.y + hid[4*h4+2]*w4.z + hid[4*h4+3]*w4.w;
        }
        lg[m] = d;
        mxl = fmaxf(mxl, d);
    }
    float se = 0.f;
#pragma unroll
    for (int m = 0; m < 8; m++){ lg[m] = expf(lg[m] - mxl); se += lg[m]; }
    float inv = 1.0f/se;
    float* dst = &g_score[(l*BB*NN*KNN + item)*MM];
    ((float4*)dst)[0] = make_float4(lg[0]*inv, lg[1]*inv, lg[2]*inv, lg[3]*inv);
    ((float4*)dst)[1] = make_float4(lg[4]*inv, lg[5]*inv, lg[6]*inv, lg[7]*inv);
}

// ---------------- 3c) build combined weights W[l][u][o] (proven) ----------------
// u < 512 : u=m*64+c -> Ktop[c, m*64+o] + Kbot[c, m*64+o]
// u >= 512: u-512=m*64+c -> -Ktop[c, m*64+o]
__global__ void k_wprep(const float* __restrict__ mats){
    int t = blockIdx.x*blockDim.x + threadIdx.x;   // 4*1024*64
    if (t >= 4*1024*OO) return;
    int l = t >> 16;
    int rest = t & 65535;
    int u = rest >> 6;
    int o = rest & 63;
    const float* ml = mats + l*128*PC;
    float v;
    if (u < 512){
        int m = u >> 6, c = u & 63;
        v = ml[c*PC + m*64 + o] + ml[(64 + c)*PC + m*64 + o];
    } else {
        int u2 = u - 512;
        int m = u2 >> 6, c = u2 & 63;
        v = -ml[c*PC + m*64 + o];
    }
    g_W[t] = v;
}

// ---------------- 4a) gather: A[n][u] (proven scalar, batch-half) ----------------
__global__ void k_gather(int l, int n0){
    int bn = n0 + blockIdx.x;              // 2048 per half
    int b  = bn >> 10;
    int tid = threadIdx.x;                 // 512
    __shared__ float s_f[KNN][64];         // 7.5KB
    __shared__ float s_sc[KNN][8];
    __shared__ float s_S[8];
    __shared__ int   s_j[KNN];
    if (tid < KNN) s_j[tid] = g_idx[bn*KNN + tid];
    if (tid < KNN*MM) ((float*)s_sc)[tid] = g_score[(l*BB*NN + bn)*KNN*MM + tid];
    __syncthreads();
    for (int q = tid; q < KNN*64; q += 512){
        int k = q >> 6, c = q & 63;
        s_f[k][c] = g_feats[(b*NN + s_j[k])*FE + l*OO + c];
    }
    if (tid < 8){
        float s = 0.f;
#pragma unroll
        for (int k = 0; k < KNN; k++) s += s_sc[k][tid];
        s_S[tid] = s;
    }
    __syncthreads();
    int m = tid >> 6;                      // 0..7 (warp-uniform)
    int c = tid & 63;
    float acc = 0.f;
#pragma unroll
    for (int k = 0; k < KNN; k++) acc += s_sc[k][m]*s_f[k][c];
    g_A[bn*1024 + tid]       = acc;                              // u = m*64+c = tid
    g_A[bn*1024 + 512 + tid] = s_S[m]*g_feats[bn*FE + l*OO + c]; // center half
}

// ---------------- 4b) out GEMM: out = A[n][1024] @ W[l] -> bn/relu (redesigned) ----------------
__global__ void k_out(int l, int n0){
    __shared__ float sA[64][16];           // [u][r]  4KB
    __shared__ float sW[64][64];           // [u][o] 16KB
    int p0 = n0 + blockIdx.x*16;           // 128 blocks per half
    int tid = threadIdx.x;                 // 256
    int og = tid & 63;
    int rg = tid >> 6;                     // 0..3 -> rows 4rg..4rg+3
    const float* Wl = g_W + l*1024*OO;
    u64 a0 = 0ULL, a1 = 0ULL;
    for (int ch = 0; ch < 16; ch++){
        for (int q = tid; q < 1024; q += 256){
            int r = q >> 6, u = q & 63;    // consecutive tid -> consecutive u (coalesced)
            sA[u][r] = g_A[(p0 + r)*1024 + ch*64 + u];
        }
        for (int q = tid; q < 4096; q += 256){
            int u = q >> 6, o = q & 63;    // coalesced
            sW[u][o] = Wl[(ch*64 + u)*OO + o];
        }
        __syncthreads();
#pragma unroll
        for (int u = 0; u < 64; u++){
            float w = sW[u][og];           // warp: og consecutive -> conflict-free
            u64 w2 = pack2(w, w);
            ulonglong2 v = *(const ulonglong2*)&sA[u][4*rg];  // warp broadcast
            ffma2(a0, v.x, w2);
            ffma2(a1, v.y, w2);
        }
        __syncthreads();
    }
    float v0, v1, v2, v3;
    unpack2(v0, v1, a0);
    unpack2(v2, v3, a1);
    g_feats[(p0 + 4*rg    )*FE + (l+1)*OO + og] = fmaxf(v0*BN_SCALE, 0.f);
    g_feats[(p0 + 4*rg + 1)*FE + (l+1)*OO + og] = fmaxf(v1*BN_SCALE, 0.f);
    g_feats[(p0 + 4*rg + 2)*FE + (l+1)*OO + og] = fmaxf(v2*BN_SCALE, 0.f);
    g_feats[(p0 + 4*rg + 3)*FE + (l+1)*OO + og] = fmaxf(v3*BN_SCALE, 0.f);
}

// ---------------- 5) final GEMM + max, packed f32x2, 2 cols/thread ----------------
__global__ void k_final(const float* __restrict__ convt_w, float* __restrict__ out){
    __shared__ float sxx[FE][18];          // [c][16 rows], pad 18 (even)
    int p0 = blockIdx.x*16;                // 256 blocks
    int b  = p0 >> 10;
    int tid = threadIdx.x;                 // 256
    for (int q = tid; q < 16*FE; q += 256){
        int r = q / FE, c = q - r*FE;
        sxx[c][r] = g_feats[p0*FE + q];
    }
    __syncthreads();
    int o1 = tid, o2 = tid + 256;
    const float* w1p = convt_w + o1*FE;
    const float* w2p = convt_w + o2*FE;
    u64 acc1[8], acc2[8];
#pragma unroll
    for (int r = 0; r < 8; r++){ acc1[r] = 0ULL; acc2[r] = 0ULL; }
#pragma unroll 2
    for (int c4 = 0; c4 < FE/4; c4++){
        float4 wa = *(const float4*)(w1p + c4*4);
        float4 wb = *(const float4*)(w2p + c4*4);
        float va[4] = {wa.x, wa.y, wa.z, wa.w};
        float vb[4] = {wb.x, wb.y, wb.z, wb.w};
#pragma unroll
        for (int s = 0; s < 4; s++){
            int c = c4*4 + s;
            u64 w1x2 = pack2(va[s], va[s]);
            u64 w2x2 = pack2(vb[s], vb[s]);
#pragma unroll
            for (int r = 0; r < 8; r++){
                u64 x2 = *(const u64*)&sxx[c][2*r];
                ffma2(acc1[r], x2, w1x2);
                ffma2(acc2[r], x2, w2x2);
            }
        }
    }
    float mx1 = 0.f, mx2 = 0.f;
#pragma unroll
    for (int r = 0; r < 8; r++){
        float lo, hi;
        unpack2(lo, hi, acc1[r]);
        mx1 = fmaxf(mx1, fmaxf(lo, hi)*BN_SCALE);
        unpack2(lo, hi, acc2[r]);
        mx2 = fmaxf(mx2, fmaxf(lo, hi)*BN_SCALE);
    }
    atomicMax((int*)&out[b*PC + o1], __float_as_int(mx1));
    atomicMax((int*)&out[b*PC + o2], __float_as_int(mx2));
}

// ---------------- launch: fork layer pipeline into 2 streams by batch-half ----------------
extern "C" void kernel_launch(void* const* d_in, const int* in_sizes, int n_in,
                              void* d_out, int out_size){
    const float* x       = (const float*)d_in[0];
    const float* conv1_w = (const float*)d_in[3];
    const float* conv1_b = (const float*)d_in[4];
    const float* sn_hw   = (const float*)d_in[5];
    const float* sn_ow   = (const float*)d_in[6];
    const float* sn_ob   = (const float*)d_in[7];
    const float* mats    = (const float*)d_in[8];
    const float* convt_w = (const float*)d_in[9];
    float* out = (float*)d_out;

    // prologue on the main (capture) stream
    k_prep<<<(BB*NN + 255)/256, 256>>>(x, out);
    k_knn<<<BB*NN, 256>>>();
    k_edge<<<BB*NN/4, 256>>>(conv1_w, conv1_b);
    k_score<<<(BB*NN*KNN/256)*4, 256>>>(sn_hw, sn_ow, sn_ob);
    k_wprep<<<(4*1024*OO + 255)/256, 256>>>(mats);

    // fork: batches 2,3 on a second stream
    cudaStream_t s2;
    cudaStreamCreateWithFlags(&s2, cudaStreamNonBlocking);
    cudaEvent_t eFork, eJoin;
    cudaEventCreateWithFlags(&eFork, cudaEventDisableTiming);
    cudaEventCreateWithFlags(&eJoin, cudaEventDisableTiming);
    cudaEventRecord(eFork, 0);
    cudaStreamWaitEvent(s2, eFork, 0);

    for (int l = 0; l < 4; l++){
        k_gather<<<2*NN, 512>>>(l, 0);                  // batches 0,1 on main stream
        k_out<<<2*NN/16, 256>>>(l, 0);
    }
    for (int l = 0; l < 4; l++){
        k_gather<<<2*NN, 512, 0, s2>>>(l, 2*NN);        // batches 2,3 on s2
        k_out<<<2*NN/16, 256, 0, s2>>>(l, 2*NN);
    }

    // join
    cudaEventRecord(eJoin, s2);
    cudaStreamWaitEvent(0, eJoin, 0);

    k_final<<<BB*NN/16, 256>>>(convt_w, out);
}

// round 16
// speedup vs baseline: 1.9433x; 1.9433x over previous
#include <cuda_runtime.h>
#include <cuda_fp16.h>
#include <math.h>

#define BB   4
#define NN   1024
#define KNN  30
#define MM   8
#define CINV 9
#define OO   64
#define FE   320
#define PC   512          // M*O
#define BN_SCALE 0.99999500003749972f

// ---------------- packed f32x2 helpers (u64 carriers) ----------------
typedef unsigned long long u64;
__device__ __forceinline__ void ffma2(u64& d, u64 a, u64 b){
    asm("fma.rn.f32x2 %0, %1, %2, %0;" : "+l"(d) : "l"(a), "l"(b));
}
__device__ __forceinline__ u64 pack2(float lo, float hi){
    u64 d; asm("mov.b64 %0, {%1,%2};" : "=l"(d) : "f"(lo), "f"(hi)); return d;
}
__device__ __forceinline__ void unpack2(float& lo, float& hi, u64 d){
    asm("mov.b64 {%0,%1}, %2;" : "=f"(lo), "=f"(hi) : "l"(d));
}

// ---------------- device scratch (no allocs allowed) ----------------
__device__ float  g_xt[BB*NN*CINV];
__device__ float  g_sq[BB*NN];
__device__ int    g_idx[BB*NN*KNN];
__device__ float  g_xyz[BB*NN*KNN*28];
__device__ float  g_feats[BB*NN*FE];
__device__ __half g_pointh[BB*NN*PC];      // fp16 point (gathered 30x per point)
__device__ float  g_center[BB*NN*PC];      // fp32 center (read once per point)
__device__ float  g_score[4*BB*NN*KNN*MM]; // [l][bn][k][m]

// ---------------- 1) transpose + sq (+ zero out) ----------------
__global__ void k_prep(const float* __restrict__ x, float* __restrict__ out){
    int t = blockIdx.x*blockDim.x + threadIdx.x;
    if (t < BB*PC) out[t] = 0.f;
    if (t >= BB*NN) return;
    int b = t >> 10, n = t & 1023;
    float s = 0.f;
#pragma unroll
    for (int c = 0; c < CINV; c++){
        float v = x[(b*CINV + c)*NN + n];
        g_xt[t*CINV + c] = v;
        s += v*v;
    }
    g_sq[t] = s;
}

// ---------------- 2) knn top-K: block per point, argmax extraction ----------------
__global__ void k_knn(){
    __shared__ unsigned long long keys[NN];   // 8KB
    __shared__ unsigned long long wmax[8];
    __shared__ float sc[CINV];
    int bn  = blockIdx.x;
    int b   = bn >> 10;
    int tid = threadIdx.x;                    // 256
    if (tid < CINV) sc[tid] = g_xt[bn*CINV + tid];
    __syncthreads();
    float c[CINV];
#pragma unroll
    for (int t = 0; t < CINV; t++) c[t] = sc[t];
    float sqi = g_sq[bn];
    for (int j = tid; j < NN; j += 256){
        const float* p = &g_xt[(b*NN + j)*CINV];
        float d = 0.f;
#pragma unroll
        for (int t = 0; t < CINV; t++) d += c[t]*p[t];
        float v = 2.0f*d - sqi - g_sq[b*NN + j];
        int iv = __float_as_int(v);
        unsigned int u = (iv >= 0) ? ((unsigned)iv | 0x80000000u) : ~((unsigned)iv);
        keys[j] = ((unsigned long long)u << 32) | (unsigned)(NN - j);
    }
    __syncthreads();
    for (int s = 0; s < KNN; s++){
        unsigned long long m = 0ULL;
#pragma unroll
        for (int r = 0; r < NN/256; r++){
            unsigned long long kk = keys[tid + r*256];
            if (kk > m) m = kk;
        }
#pragma unroll
        for (int off = 16; off; off >>= 1){
            unsigned long long o = __shfl_down_sync(0xFFFFFFFFu, m, off);
            if (o > m) m = o;
        }
        if ((tid & 31) == 0) wmax[tid >> 5] = m;
        __syncthreads();
        if (tid == 0){
            unsigned long long mm = wmax[0];
#pragma unroll
            for (int w = 1; w < 8; w++) if (wmax[w] > mm) mm = wmax[w];
            int j = NN - (int)(mm & 0xFFFFFFFFULL);
            g_idx[bn*KNN + s] = j;
            keys[j] = 0ULL;
        }
        __syncthreads();
    }
}

// ---------------- 3) xyz build + conv1->bn->relu->max_k (4 points/block) ----------------
__global__ void k_edge(const float* __restrict__ w1, const float* __restrict__ b1){
    int p0  = blockIdx.x*4;                // 1024 blocks
    int tid = threadIdx.x;                 // 256
    int lp  = tid >> 6;                    // local point 0..3
    int o   = tid & 63;                    // channel
    __shared__ float s_w1[64*18];
    __shared__ float s_b1[64];
    __shared__ float s_gf[4][KNN][18];
    __shared__ float s_ctr[4][CINV];
    for (int q = tid; q < 64*18; q += 256) s_w1[q] = w1[q];
    if (tid < 64) s_b1[tid] = b1[tid];
    if (tid < 4*CINV) s_ctr[tid/CINV][tid%CINV] = g_xt[(p0 + tid/CINV)*CINV + tid%CINV];
    __syncthreads();
    if (tid < 4*KNN){
        int lp2 = tid / KNN;
        int k   = tid - lp2*KNN;
        int bn  = p0 + lp2;
        int b   = bn >> 10;
        int j   = g_idx[bn*KNN + k];
        float nb[CINV], df[CINV]; float ss = 0.f;
#pragma unroll
        for (int t = 0; t < CINV; t++){
            float ct = s_ctr[lp2][t];
            nb[t] = g_xt[(b*NN + j)*CINV + t];
            df[t] = nb[t] - ct;
            ss += df[t]*df[t];
        }
        float* xz = &g_xyz[(bn*KNN + k)*28];
#pragma unroll
        for (int t = 0; t < CINV; t++){
            xz[t]      = df[t];
            xz[9 + t]  = nb[t];
            xz[18 + t] = s_ctr[lp2][t];
            s_gf[lp2][k][t]     = df[t];
            s_gf[lp2][k][9 + t] = s_ctr[lp2][t];
        }
        xz[27] = sqrtf(ss);
    }
    __syncthreads();
    float w[18];
#pragma unroll
    for (int t = 0; t < 18; t++) w[t] = s_w1[o*18 + t];
    float bias = s_b1[o];
    float mx = 0.f;
    for (int k = 0; k < KNN; k++){
        float d = bias;
#pragma unroll
        for (int t = 0; t < 18; t++) d += s_gf[lp][k][t]*w[t];
        mx = fmaxf(mx, d*BN_SCALE);
    }
    g_feats[(p0 + lp)*FE + o] = mx;
}

// ---------------- 3b) scorenet: one layer per block (proven scalar version) ----------------
__global__ void k_score(const float* __restrict__ hw, const float* __restrict__ ow,
                        const float* __restrict__ ob){
    __shared__ float s_hw[448];
    __shared__ float s_ow[128];
    __shared__ float s_ob[8];
    int tid = threadIdx.x;                 // 256
    int l   = blockIdx.x & 3;
    int item = (blockIdx.x >> 2)*256 + tid;    // bn*KNN + k
    for (int q = tid; q < 448; q += 256) s_hw[q] = hw[l*448 + q];
    if (tid < 128) s_ow[tid] = ow[l*128 + tid];
    if (tid < 8)   s_ob[tid] = ob[l*8 + tid];
    __syncthreads();
    float xr[28];
    const float4* xz4 = (const float4*)(g_xyz + item*28);
#pragma unroll
    for (int v = 0; v < 7; v++) ((float4*)xr)[v] = xz4[v];
    float hid[16];
#pragma unroll
    for (int h = 0; h < 16; h++){
        float d = 0.f;
#pragma unroll
        for (int t = 0; t < 28; t++) d += xr[t]*s_hw[h*28 + t];
        hid[h] = fmaxf(d*BN_SCALE, 0.f);
    }
    float lg[8]; float mxl = -3.4e38f;
#pragma unroll
    for (int m = 0; m < 8; m++){
        float d = s_ob[m];
#pragma unroll
        for (int h = 0; h < 16; h++) d += hid[h]*s_ow[m*16 + h];
        lg[m] = d;
        mxl = fmaxf(mxl, d);
    }
    float se = 0.f;
#pragma unroll
    for (int m = 0; m < 8; m++){ lg[m] = expf(lg[m] - mxl); se += lg[m]; }
    float inv = 1.0f/se;
    float* dst = &g_score[(l*BB*NN*KNN + item)*MM];
    ((float4*)dst)[0] = make_float4(lg[0]*inv, lg[1]*inv, lg[2]*inv, lg[3]*inv);
    ((float4*)dst)[1] = make_float4(lg[4]*inv, lg[5]*inv, lg[6]*inv, lg[7]*inv);
}

// ---------------- 4a) point & center GEMM, f32x2 + coalesced mats (batch-half) ----------------
__global__ void k_point(const float* __restrict__ mats, int l, int n0){
    __shared__ float sf[64][16];           // [c][r] — u64 row-pair broadcast reads
    int p0 = n0 + blockIdx.x*16;
    int j  = threadIdx.x;                  // 512 output columns
    for (int q = threadIdx.x; q < 16*OO; q += 512){
        int r = q >> 6, c = q & 63;        // coalesced gmem read
        sf[c][r] = g_feats[(p0 + r)*FE + l*OO + c];
    }
    __syncthreads();
    const float* kern = mats + l*128*PC;
    u64 a1[8], a2[8];
#pragma unroll
    for (int r = 0; r < 8; r++){ a1[r] = 0ULL; a2[r] = 0ULL; }
#pragma unroll 4
    for (int c4 = 0; c4 < 16; c4++){
        int c = c4*4;
        float k10 = kern[(c+0)*PC + j], k11 = kern[(c+1)*PC + j];
        float k12 = kern[(c+2)*PC + j], k13 = kern[(c+3)*PC + j];
        float k20 = kern[(c+64)*PC + j], k21 = kern[(c+65)*PC + j];
        float k22 = kern[(c+66)*PC + j], k23 = kern[(c+67)*PC + j];
        float ka[4] = {k10, k11, k12, k13};
        float kb[4] = {k20, k21, k22, k23};
#pragma unroll
        for (int s = 0; s < 4; s++){
            u64 ka2 = pack2(ka[s], ka[s]);
            u64 kb2 = pack2(kb[s], kb[s]);
#pragma unroll
            for (int r = 0; r < 8; r++){
                u64 x2 = *(const u64*)&sf[c + s][2*r];
                ffma2(a1[r], x2, ka2);
                ffma2(a2[r], x2, kb2);
            }
        }
    }
#pragma unroll
    for (int r = 0; r < 8; r++){
        float c0, c1, b0, b1;
        unpack2(c0, c1, a1[r]);
        unpack2(b0, b1, a2[r]);
        g_center[(p0 + 2*r    )*PC + j] = c0;
        g_center[(p0 + 2*r + 1)*PC + j] = c1;
        g_pointh[(p0 + 2*r    )*PC + j] = __float2half(c0 + b0);
        g_pointh[(p0 + 2*r + 1)*PC + j] = __float2half(c1 + b1);
    }
}

// ---------------- 4b) gather(fp16) + assemble + bn/relu (256 thr, 16-way k) ----------------
__global__ void k_asm(int l, int n0){
    int bn = n0 + blockIdx.x;
    int b  = bn >> 10;
    int tid = threadIdx.x;             // 256
    __shared__ float  s_sc[KNN][8];
    __shared__ float  s_S[8];
    __shared__ int    s_j[KNN];
    __shared__ float4 s_part[16][16];  // [kp][quad]
    if (tid < KNN) s_j[tid] = g_idx[bn*KNN + tid];
    if (tid < KNN*MM) ((float*)s_sc)[tid] = g_score[(l*BB*NN + bn)*KNN*MM + tid];
    __syncthreads();
    if (tid < 8){
        float s = 0.f;
#pragma unroll
        for (int k = 0; k < KNN; k++) s += s_sc[k][tid];
        s_S[tid] = s;
    }
    int q  = tid & 15;                 // o-quad: channels 4q..4q+3
    int kp = tid >> 4;                 // k partition 0..15
    float4 acc = make_float4(0.f, 0.f, 0.f, 0.f);
    for (int k = kp; k < KNN; k += 16){
        const __half* pr = &g_pointh[(b*NN + s_j[k])*PC + 4*q];
#pragma unroll
        for (int m = 0; m < 8; m++){
            float s = s_sc[k][m];
            uint2 raw = *(const uint2*)(pr + m*OO);
            float2 f0 = __half22float2(*(const __half2*)&raw.x);
            float2 f1 = __half22float2(*(const __half2*)&raw.y);
            acc.x += s*f0.x; acc.y += s*f0.y; acc.z += s*f1.x; acc.w += s*f1.y;
        }
    }
    s_part[kp][q] = acc;
    __syncthreads();
    if (tid < OO){
        int o = tid, qq = o >> 2, cc = o & 3;
        float a = 0.f;
#pragma unroll
        for (int kp2 = 0; kp2 < 16; kp2++){
            const float* pp = (const float*)&s_part[kp2][qq];
            a += pp[cc];
        }
        const float* cr = &g_center[bn*PC + o];
#pragma unroll
        for (int m = 0; m < 8; m++) a -= s_S[m]*cr[m*OO];
        g_feats[bn*FE + (l+1)*OO + o] = fmaxf(a*BN_SCALE, 0.f);
    }
}

// ---------------- 5) final GEMM + max, packed f32x2, 2 cols/thread ----------------
__global__ void k_final(const float* __restrict__ convt_w, float* __restrict__ out){
    __shared__ float sxx[FE][18];          // [c][16 rows], pad 18 (even)
    int p0 = blockIdx.x*16;                // 256 blocks
    int b  = p0 >> 10;
    int tid = threadIdx.x;                 // 256
    for (int q = tid; q < 16*FE; q += 256){
        int r = q / FE, c = q - r*FE;
        sxx[c][r] = g_feats[p0*FE + q];
    }
    __syncthreads();
    int o1 = tid, o2 = tid + 256;
    const float* w1p = convt_w + o1*FE;
    const float* w2p = convt_w + o2*FE;
    u64 acc1[8], acc2[8];
#pragma unroll
    for (int r = 0; r < 8; r++){ acc1[r] = 0ULL; acc2[r] = 0ULL; }
#pragma unroll 2
    for (int c4 = 0; c4 < FE/4; c4++){
        float4 wa = *(const float4*)(w1p + c4*4);
        float4 wb = *(const float4*)(w2p + c4*4);
        float va[4] = {wa.x, wa.y, wa.z, wa.w};
        float vb[4] = {wb.x, wb.y, wb.z, wb.w};
#pragma unroll
        for (int s = 0; s < 4; s++){
            int c = c4*4 + s;
            u64 w1x2 = pack2(va[s], va[s]);
            u64 w2x2 = pack2(vb[s], vb[s]);
#pragma unroll
            for (int r = 0; r < 8; r++){
                u64 x2 = *(const u64*)&sxx[c][2*r];
                ffma2(acc1[r], x2, w1x2);
                ffma2(acc2[r], x2, w2x2);
            }
        }
    }
    float mx1 = 0.f, mx2 = 0.f;
#pragma unroll
    for (int r = 0; r < 8; r++){
        float lo, hi;
        unpack2(lo, hi, acc1[r]);
        mx1 = fmaxf(mx1, fmaxf(lo, hi)*BN_SCALE);
        unpack2(lo, hi, acc2[r]);
        mx2 = fmaxf(mx2, fmaxf(lo, hi)*BN_SCALE);
    }
    atomicMax((int*)&out[b*PC + o1], __float_as_int(mx1));
    atomicMax((int*)&out[b*PC + o2], __float_as_int(mx2));
}

// ---------------- launch: fork layer pipeline into 2 streams by batch-half ----------------
extern "C" void kernel_launch(void* const* d_in, const int* in_sizes, int n_in,
                              void* d_out, int out_size){
    const float* x       = (const float*)d_in[0];
    const float* conv1_w = (const float*)d_in[3];
    const float* conv1_b = (const float*)d_in[4];
    const float* sn_hw   = (const float*)d_in[5];
    const float* sn_ow   = (const float*)d_in[6];
    const float* sn_ob   = (const float*)d_in[7];
    const float* mats    = (const float*)d_in[8];
    const float* convt_w = (const float*)d_in[9];
    float* out = (float*)d_out;

    // prologue on the main (capture) stream
    k_prep<<<(BB*NN + 255)/256, 256>>>(x, out);
    k_knn<<<BB*NN, 256>>>();
    k_edge<<<BB*NN/4, 256>>>(conv1_w, conv1_b);
    k_score<<<(BB*NN*KNN/256)*4, 256>>>(sn_hw, sn_ow, sn_ob);

    // fork: batches 2,3 on a second stream
    cudaStream_t s2;
    cudaStreamCreateWithFlags(&s2, cudaStreamNonBlocking);
    cudaEvent_t eFork, eJoin;
    cudaEventCreateWithFlags(&eFork, cudaEventDisableTiming);
    cudaEventCreateWithFlags(&eJoin, cudaEventDisableTiming);
    cudaEventRecord(eFork, 0);
    cudaStreamWaitEvent(s2, eFork, 0);

    for (int l = 0; l < 4; l++){
        k_point<<<2*NN/16, 512>>>(mats, l, 0);          // batches 0,1 on main stream
        k_asm<<<2*NN, 256>>>(l, 0);
    }
    for (int l = 0; l < 4; l++){
        k_point<<<2*NN/16, 512, 0, s2>>>(mats, l, 2*NN); // batches 2,3 on s2
        k_asm<<<2*NN, 256, 0, s2>>>(l, 2*NN);
    }

    // join
    cudaEventRecord(eJoin, s2);
    cudaStreamWaitEvent(0, eJoin, 0);

    k_final<<<BB*NN/16, 256>>>(convt_w, out);
}